// round 9
// baseline (speedup 1.0000x reference)
#include <cuda_runtime.h>
#include <cuda_bf16.h>
#include <math.h>
#include <cstdint>

// Problem constants
#define BX   4
#define TT   1024
#define SS   1024
#define EE   1024
#define HH   16
#define DH   64

// Scratch (device globals; no allocation allowed)
__device__ float g_Q[BX * HH * TT * DH];   // [B,H,T,D]  tf32, pre-scaled by 1/8
__device__ float g_K[BX * HH * SS * DH];   // [B,H,S,D]  tf32
__device__ float g_Vt[BX * HH * DH * SS];  // [B,H,D,S]  tf32
__device__ float g_P[TT * BX * EE];        // [T,B,E]    tf32
__device__ float g_Wt[4 * EE * EE];        // W^T [N,K]  tf32
__device__ float g_Ar[BX * TT * EE];       // tgt tf32-rounded
__device__ float g_Br[BX * SS * EE];       // src tf32-rounded

// ---------------------------------------------------------------------------
// Helpers
// ---------------------------------------------------------------------------
__device__ __forceinline__ uint32_t smem_u32(const void* p) {
    uint32_t a;
    asm("{ .reg .u64 t; cvta.to.shared.u64 t, %1; cvt.u32.u64 %0, t; }" : "=r"(a) : "l"(p));
    return a;
}
__device__ __forceinline__ float tf32r(float x) {
    uint32_t u;
    asm("cvt.rna.tf32.f32 %0, %1;" : "=r"(u) : "f"(x));
    return __uint_as_float(u);
}
#define SWZ128(off) ((off) ^ (((off) >> 3) & 0x70))

__device__ __forceinline__ void cp16(uint32_t dst, const void* src) {
    asm volatile("cp.async.cg.shared.global [%0], [%1], 16;" :: "r"(dst), "l"(src));
}
#define CP_COMMIT() asm volatile("cp.async.commit_group;" ::: "memory")
#define CP_WAIT1()  asm volatile("cp.async.wait_group 1;" ::: "memory")

__device__ __forceinline__ void ldsm4(uint32_t* r, uint32_t addr) {
    asm volatile("ldmatrix.sync.aligned.m8n8.x4.shared.b16 {%0,%1,%2,%3}, [%4];"
                 : "=r"(r[0]), "=r"(r[1]), "=r"(r[2]), "=r"(r[3]) : "r"(addr));
}
__device__ __forceinline__ void mma_tf32(float* d, const uint32_t* a, uint32_t b0, uint32_t b1) {
    asm volatile("mma.sync.aligned.m16n8k8.row.col.f32.tf32.tf32.f32 "
                 "{%0,%1,%2,%3}, {%4,%5,%6,%7}, {%8,%9}, {%0,%1,%2,%3};"
                 : "+f"(d[0]), "+f"(d[1]), "+f"(d[2]), "+f"(d[3])
                 : "r"(a[0]), "r"(a[1]), "r"(a[2]), "r"(a[3]), "r"(b0), "r"(b1));
}

// ---------------------------------------------------------------------------
// Elementwise tf32 rounding copies (z selects tensor)
// ---------------------------------------------------------------------------
__global__ __launch_bounds__(256)
void round_tf32_kernel(const float* __restrict__ a, const float* __restrict__ b,
                       float* __restrict__ oa, float* __restrict__ ob)
{
    const float* src = blockIdx.z ? b : a;
    float* dst = blockIdx.z ? ob : oa;
    const int n4 = (BX * TT * EE) / 4;
    for (int i = blockIdx.x * 256 + threadIdx.x; i < n4; i += gridDim.x * 256) {
        float4 v = ((const float4*)src)[i];
        v.x = tf32r(v.x); v.y = tf32r(v.y); v.z = tf32r(v.z); v.w = tf32r(v.w);
        ((float4*)dst)[i] = v;
    }
}

// ---------------------------------------------------------------------------
// Weight transpose + tf32 round, 4 weights in one launch (z selects)
// ---------------------------------------------------------------------------
__global__ __launch_bounds__(256)
void transpose_tf32_kernel(const float* __restrict__ W0, const float* __restrict__ W1,
                           const float* __restrict__ W2, const float* __restrict__ W3,
                           float* __restrict__ WtBase)
{
    __shared__ float tile[32][33];
    const int z = blockIdx.z;
    const float* W = (z == 0) ? W0 : (z == 1) ? W1 : (z == 2) ? W2 : W3;
    float* Wt = WtBase + (size_t)z * EE * EE;
    const int k0 = blockIdx.y * 32, n0 = blockIdx.x * 32;
    const int tx = threadIdx.x & 31, ty = threadIdx.x >> 5;
#pragma unroll
    for (int t = 0; t < 4; t++)
        tile[ty + 8 * t][tx] = W[(size_t)(k0 + ty + 8 * t) * EE + n0 + tx];
    __syncthreads();
#pragma unroll
    for (int t = 0; t < 4; t++)
        Wt[(size_t)(n0 + ty + 8 * t) * EE + k0 + tx] = tf32r(tile[tx][ty + 8 * t]);
}

// ---------------------------------------------------------------------------
// tf32 mma.sync GEMM body (unchanged)
// ---------------------------------------------------------------------------
#define GSMEM (3 * 32768 + 1024)

__device__ __forceinline__ void gemm_body(
    const float* __restrict__ A, const float* __restrict__ Bt,
    const float* __restrict__ bias, float* __restrict__ C,
    int mode, float scale, int L)
{
    extern __shared__ char dyn_sm[];
    char* sm = (char*)(((uintptr_t)dyn_sm + 1023) & ~(uintptr_t)1023);
    const uint32_t sb = smem_u32(sm);

    const int tid  = threadIdx.x;
    const int wid  = tid >> 5;
    const int lane = tid & 31;
    const int wm   = wid & 3;
    const int wn   = wid >> 2;
    const int m0 = blockIdx.y * 128;
    const int n0 = blockIdx.x * 128;

    const float* Ap = A  + (size_t)m0 * 1024;
    const float* Bp = Bt + (size_t)n0 * 1024;

    const int lrow  = ((lane >> 3) & 1) * 8 + (lane & 7);
    const int klane = lane >> 4;

    uint32_t aoff[2], asw[2], boff[4], bsw[4];
#pragma unroll
    for (int mt = 0; mt < 2; mt++) {
        int r = wm * 32 + mt * 16 + lrow;
        aoff[mt] = (uint32_t)r * 128;
        asw[mt]  = (uint32_t)(r & 7);
    }
#pragma unroll
    for (int nt = 0; nt < 4; nt++) {
        int r = wn * 64 + nt * 16 + lrow;
        boff[nt] = (uint32_t)r * 128;
        bsw[nt]  = (uint32_t)(r & 7);
    }

    float acc[2][8][4];
#pragma unroll
    for (int mt = 0; mt < 2; mt++)
#pragma unroll
        for (int nt = 0; nt < 8; nt++)
#pragma unroll
            for (int c = 0; c < 4; c++) acc[mt][nt][c] = 0.f;

    auto prefetch = [&](int st, int kt) {
        const int k0 = kt * 32;
        const uint32_t ao = sb + st * 32768;
        const uint32_t bo = ao + 16384;
#pragma unroll
        for (int t = 0; t < 4; t++) {
            int idx = tid + t * 256;
            int r = idx >> 3, c4 = idx & 7;
            uint32_t sw = SWZ128((uint32_t)(r * 128 + c4 * 16));
            cp16(ao + sw, Ap + (size_t)r * 1024 + k0 + c4 * 4);
            cp16(bo + sw, Bp + (size_t)r * 1024 + k0 + c4 * 4);
        }
    };

    prefetch(0, 0); CP_COMMIT();
    prefetch(1, 1); CP_COMMIT();

#pragma unroll 1
    for (int kt = 0; kt < 32; kt++) {
        CP_WAIT1();
        __syncthreads();
        if (kt + 2 < 32) prefetch((kt + 2) % 3, kt + 2);
        CP_COMMIT();

        const uint32_t ab = sb + (kt % 3) * 32768;
        const uint32_t bb = ab + 16384;
#pragma unroll
        for (int k8 = 0; k8 < 4; k8++) {
            const uint32_t kc = (uint32_t)(k8 * 2 + klane);
            uint32_t af[2][4], bf[4][4];
#pragma unroll
            for (int mt = 0; mt < 2; mt++)
                ldsm4(af[mt], ab + aoff[mt] + ((kc ^ asw[mt]) << 4));
#pragma unroll
            for (int nt = 0; nt < 4; nt++)
                ldsm4(bf[nt], bb + boff[nt] + ((kc ^ bsw[nt]) << 4));
#pragma unroll
            for (int mt = 0; mt < 2; mt++)
#pragma unroll
                for (int n8 = 0; n8 < 8; n8++) {
                    int bt = n8 >> 1, sub = n8 & 1;
                    mma_tf32(acc[mt][n8], af[mt], bf[bt][sub], bf[bt][sub + 2]);
                }
        }
    }

    const int rbase = lane >> 2;
    const int cbase = 2 * (lane & 3);
#pragma unroll
    for (int mt = 0; mt < 2; mt++) {
#pragma unroll
        for (int nt = 0; nt < 8; nt++) {
            int n = n0 + wn * 64 + nt * 8 + cbase;
#pragma unroll
            for (int half = 0; half < 2; half++) {
                int m = m0 + wm * 32 + mt * 16 + rbase + half * 8;
                float2 v;
                v.x = acc[mt][nt][half * 2 + 0];
                v.y = acc[mt][nt][half * 2 + 1];
                if (mode == 0) {
                    v.x += bias[n];
                    v.y += bias[n + 1];
                    *(float2*)&C[(size_t)m * 1024 + n] = v;
                } else if (mode == 1) {
                    int b = m / L, l = m % L;
                    size_t o = (((size_t)(b * HH + (n >> 6)) * L + l) * DH) + (n & 63);
                    v.x = tf32r(v.x * scale);
                    v.y = tf32r(v.y * scale);
                    *(float2*)&C[o] = v;
                } else {
                    int b = m / L, s = m % L;
                    size_t o = (((size_t)(b * HH + (n >> 6)) * DH) + (n & 63)) * (size_t)L + s;
                    C[o]     = tf32r(v.x);
                    C[o + L] = tf32r(v.y);
                }
            }
        }
    }
}

__global__ __launch_bounds__(256)
void gemm_qkv_kernel(const float* __restrict__ Atgt, const float* __restrict__ Asrc,
                     const float* __restrict__ Wt,
                     float* __restrict__ Cq, float* __restrict__ Ck, float* __restrict__ Cvt)
{
    const int z = blockIdx.z;
    const float* A = (z == 0) ? Atgt : Asrc;
    const float* W = Wt + (size_t)z * EE * EE;
    float* C = (z == 0) ? Cq : (z == 1) ? Ck : Cvt;
    gemm_body(A, W, nullptr, C, (z == 2) ? 2 : 1, (z == 0) ? 0.125f : 1.0f, (z == 0) ? TT : SS);
}

__global__ __launch_bounds__(256)
void gemm_out_kernel(const float* __restrict__ A, const float* __restrict__ Wt,
                     const float* __restrict__ bias, float* __restrict__ C)
{
    gemm_body(A, Wt, bias, C, 0, 1.0f, TT);
}

// ---------------------------------------------------------------------------
// Fused flash-style attention, 256 threads (8 warps), 2 CTAs/SM.
// One block = (b,h) x 64 t-rows; 16 iterations of 64-column tiles.
// K: 3-stage cp.async (distance 2); V: 2-stage (distance 1).
// ONE barrier per iteration: commit order per iter is [V(it+1)], [K(it+2)],
// so wait_group(1) at the top guarantees K(it) and V(it) complete.
// P never touches smem (shuffle permute); PV k-split 2, reduced at end.
// ---------------------------------------------------------------------------
#define AT2 64
// smem float offsets
#define F_Q    0                    // 64x64, rows 256B swizzled      4096
#define F_K    4096                 // 3 x 64x64                     12288
#define F_V    16384                // 2 x 64x64 (V^T d x s)          8192
#define F_SP   24576                // spad row for b                 1024
#define F_PART 25600                // 2 x 64 partial row sums         128
#define F_SUM  25728                // 64 inv sums                      64
#define ATTN2_FLOATS 25856          // 103424 B
#define RED_PITCH 72                // k-split O reduce buffer (reuses F_K)

__global__ __launch_bounds__(256, 2)
void attn_kernel(const float* __restrict__ Q, const float* __restrict__ K,
                 const float* __restrict__ Vt,
                 const float* __restrict__ tpad, const float* __restrict__ spad,
                 const float* __restrict__ amask, const int* __restrict__ causal_p,
                 float* __restrict__ attn_out, float* __restrict__ P)
{
    extern __shared__ float smf[];
    const uint32_t q_b  = smem_u32(smf + F_Q);
    const uint32_t k_b  = smem_u32(smf + F_K);
    const uint32_t v_b  = smem_u32(smf + F_V);
    const uint32_t sp_b = smem_u32(smf + F_SP);
    float* s_sp   = smf + F_SP;
    float* s_part = smf + F_PART;
    float* s_sum  = smf + F_SUM;
    float* s_red  = smf + F_K;      // reused after main loop (guarded by barrier)

    const int tid = threadIdx.x;
    const int bh  = blockIdx.y;
    const int b   = bh >> 4;
    const int h   = bh & 15;
    const int t0  = blockIdx.x * AT2;
    const bool causal = (causal_p[0] != 0);

    const size_t qbase  = ((size_t)bh * TT + t0) * DH;
    const size_t kbase  = (size_t)bh * SS * DH;
    const size_t vtbase = (size_t)bh * DH * SS;

    const int lane  = tid & 31;
    const int wid   = tid >> 5;
    const int wm    = wid & 3;    // m16 group
    const int wn    = wid >> 2;   // n32 group (0/1); also PV k-split id
    const int lrow  = ((lane >> 3) & 1) * 8 + (lane & 7);
    const int klane = lane >> 4;
    const int rbase = lane >> 2;
    const int cbase = 2 * (lane & 3);

    const int r0 = wm * 16 + rbase;
    const int r1 = r0 + 8;
    const float tm0 = tpad[b * TT + t0 + r0];
    const float tm1 = tpad[b * TT + t0 + r1];

    // shuffle sources for C-layout -> A-fragment permute
    const int p_   = lane & 3;
    const int srcA = (lane & 28) | (p_ >> 1);
    const bool oddp = (p_ & 1);

    auto prefetch_k = [&](int it) {
        const uint32_t kb = k_b + (uint32_t)(it % 3) * 16384;
        const int c0 = it * 64;
#pragma unroll
        for (int t = 0; t < 4; t++) {
            int idx = tid + t * 256;
            int r = idx >> 4, c = idx & 15;
            cp16(kb + r * 256 + ((c ^ (r & 7)) << 4),
                 K + kbase + (size_t)(c0 + r) * DH + c * 4);
        }
    };
    auto prefetch_v = [&](int it) {
        const uint32_t vb = v_b + (uint32_t)(it & 1) * 16384;
        const int c0 = it * 64;
#pragma unroll
        for (int t = 0; t < 4; t++) {
            int idx = tid + t * 256;
            int r = idx >> 4, c = idx & 15;
            cp16(vb + r * 256 + ((c ^ (r & 7)) << 4),
                 Vt + vtbase + (size_t)r * SS + c0 + c * 4);
        }
    };

    // prologue group 1: Q + spad + K0 + V0 ; group 2: K1
    {
#pragma unroll
        for (int t = 0; t < 4; t++) {
            int idx = tid + t * 256;
            int r = idx >> 4, c = idx & 15;
            cp16(q_b + r * 256 + ((c ^ (r & 7)) << 4), Q + qbase + (size_t)r * DH + c * 4);
        }
        cp16(sp_b + tid * 16, spad + b * SS + tid * 4);
    }
    prefetch_k(0);
    prefetch_v(0);
    CP_COMMIT();
    prefetch_k(1);
    CP_COMMIT();

    // Q fragments loaded inside iter 0 after the first wait+sync
    const int arow = wm * 16 + lrow;
    uint32_t qf[8][4];
    const int brow0 = wn * 32 + lrow;        // K rows (first n16 of this n32)
    const int brow1 = brow0 + 16;            // second n16

    float rs0 = 0.f, rs1 = 0.f;
    float oacc[8][4];                        // m16 x n64 partial (own k slice)
#pragma unroll
    for (int n8 = 0; n8 < 8; n8++)
#pragma unroll
        for (int c = 0; c < 4; c++) oacc[n8][c] = 0.f;

#pragma unroll 1
    for (int it = 0; it < 16; it++) {
        CP_WAIT1();          // guarantees K(it), V(it), (it==0: Q, spad) complete
        __syncthreads();

        // issue next prefetches: V first, then K (order is load-bearing)
        if (it + 1 < 16) prefetch_v(it + 1);
        CP_COMMIT();
        if (it + 2 < 16) prefetch_k(it + 2);
        CP_COMMIT();

        if (it == 0) {
            // preload Q fragments (m16 rows wm*16.., k=64)
#pragma unroll
            for (int k8 = 0; k8 < 8; k8++) {
                uint32_t kc = (uint32_t)(k8 * 2 + klane);
                ldsm4(qf[k8], q_b + arow * 256 + ((kc ^ (uint32_t)(arow & 7)) << 4));
            }
        }

        const int c0 = it * 64;
        const uint32_t kb = k_b + (uint32_t)(it % 3) * 16384;
        const uint32_t vb = v_b + (uint32_t)(it & 1) * 16384;

        // mask loads early
        float2 am[4][2];
#pragma unroll
        for (int n8 = 0; n8 < 4; n8++) {
            int sc = c0 + wn * 32 + n8 * 8 + cbase;
            am[n8][0] = *(const float2*)&amask[((size_t)b * TT + t0 + r0) * SS + sc];
            am[n8][1] = *(const float2*)&amask[((size_t)b * TT + t0 + r1) * SS + sc];
        }

        // S = Q @ K^T  (warp m16 x n32)
        float acc[4][4];
#pragma unroll
        for (int n8 = 0; n8 < 4; n8++)
#pragma unroll
            for (int c = 0; c < 4; c++) acc[n8][c] = 0.f;

#pragma unroll
        for (int k8 = 0; k8 < 8; k8++) {
            uint32_t kc = (uint32_t)(k8 * 2 + klane);
            uint32_t bf0[4], bf1[4];
            ldsm4(bf0, kb + brow0 * 256 + ((kc ^ (uint32_t)(brow0 & 7)) << 4));
            ldsm4(bf1, kb + brow1 * 256 + ((kc ^ (uint32_t)(brow1 & 7)) << 4));
            mma_tf32(acc[0], qf[k8], bf0[0], bf0[2]);
            mma_tf32(acc[1], qf[k8], bf0[1], bf0[3]);
            mma_tf32(acc[2], qf[k8], bf1[0], bf1[2]);
            mma_tf32(acc[3], qf[k8], bf1[1], bf1[3]);
        }

        // exp (no max shift), attn write (unnormalized), row sums, tf32 round
        const int tg0 = t0 + r0, tg1 = t0 + r1;
#pragma unroll
        for (int n8 = 0; n8 < 4; n8++) {
            int scl = wn * 32 + n8 * 8 + cbase;
            int sc  = c0 + scl;
            float2 sp = *(const float2*)&s_sp[sc];

            float m00 = tm0 * sp.x * am[n8][0].x;
            float m01 = tm0 * sp.y * am[n8][0].y;
            float m10 = tm1 * sp.x * am[n8][1].x;
            float m11 = tm1 * sp.y * am[n8][1].y;
            if (causal) {
                if (sc > tg0)     m00 = 0.f;
                if (sc + 1 > tg0) m01 = 0.f;
                if (sc > tg1)     m10 = 0.f;
                if (sc + 1 > tg1) m11 = 0.f;
            }
            float e00 = __expf(acc[n8][0] + m00);
            float e01 = __expf(acc[n8][1] + m01);
            float e10 = __expf(acc[n8][2] + m10);
            float e11 = __expf(acc[n8][3] + m11);
            rs0 += e00 + e01;
            rs1 += e10 + e11;

            if (attn_out) {
                float2 w0 = {e00, e01}, w1 = {e10, e11};
                *(float2*)&attn_out[((size_t)bh * TT + tg0) * SS + sc] = w0;
                *(float2*)&attn_out[((size_t)bh * TT + tg1) * SS + sc] = w1;
            }
            // keep tf32-rounded P in registers (C layout)
            acc[n8][0] = tf32r(e00);
            acc[n8][1] = tf32r(e01);
            acc[n8][2] = tf32r(e10);
            acc[n8][3] = tf32r(e11);
        }

        // O += P @ V over this warp's own 32 k-columns (A-frags via shuffles)
#pragma unroll
        for (int j = 0; j < 4; j++) {
            float u0 = __shfl_sync(0xffffffffu, acc[j][0], srcA);
            float u1 = __shfl_sync(0xffffffffu, acc[j][1], srcA);
            float v0 = __shfl_sync(0xffffffffu, acc[j][2], srcA);
            float v1 = __shfl_sync(0xffffffffu, acc[j][3], srcA);
            float w0 = __shfl_sync(0xffffffffu, acc[j][0], srcA + 2);
            float w1 = __shfl_sync(0xffffffffu, acc[j][1], srcA + 2);
            float x0 = __shfl_sync(0xffffffffu, acc[j][2], srcA + 2);
            float x1 = __shfl_sync(0xffffffffu, acc[j][3], srcA + 2);
            uint32_t af[4];
            af[0] = __float_as_uint(oddp ? u1 : u0);
            af[1] = __float_as_uint(oddp ? v1 : v0);
            af[2] = __float_as_uint(oddp ? w1 : w0);
            af[3] = __float_as_uint(oddp ? x1 : x0);

            uint32_t kc = (uint32_t)((wn * 4 + j) * 2 + klane);
#pragma unroll
            for (int nt = 0; nt < 4; nt++) {
                int br = nt * 16 + lrow;
                uint32_t bf[4];
                ldsm4(bf, vb + br * 256 + ((kc ^ (uint32_t)(br & 7)) << 4));
                mma_tf32(oacc[2 * nt],     af, bf[0], bf[2]);
                mma_tf32(oacc[2 * nt + 1], af, bf[1], bf[3]);
            }
        }
        // no bottom barrier: next iter's prefetches target disjoint buffers
    }

    // row-sum reduction: quad shuffle, then 2-way cross-warp via smem
    rs0 += __shfl_xor_sync(0xffffffffu, rs0, 1);
    rs0 += __shfl_xor_sync(0xffffffffu, rs0, 2);
    rs1 += __shfl_xor_sync(0xffffffffu, rs1, 1);
    rs1 += __shfl_xor_sync(0xffffffffu, rs1, 2);

    __syncthreads();   // all warps out of main loop before s_red reuses K buffer

    if ((lane & 3) == 0) {
        s_part[wn * 64 + r0] = rs0;
        s_part[wn * 64 + r1] = rs1;
    }
    // k-split partials: wn==1 stores O partial to s_red (reuses K buffer)
    if (wn == 1) {
#pragma unroll
        for (int n8 = 0; n8 < 8; n8++) {
            int cc = n8 * 8 + cbase;
            *(float2*)&s_red[r0 * RED_PITCH + cc] = *(float2*)&oacc[n8][0];
            *(float2*)&s_red[r1 * RED_PITCH + cc] = *(float2*)&oacc[n8][2];
        }
    }
    __syncthreads();
    if (tid < 64) {
        s_sum[tid] = 1.f / (s_part[tid] + s_part[64 + tid]);
    }
    __syncthreads();

    // wn==0 warps: combine k-split partials, scale, write P gmem (tf32)
    if (wn == 0) {
        float inv0 = s_sum[r0], inv1 = s_sum[r1];
#pragma unroll
        for (int n8 = 0; n8 < 8; n8++) {
            int cc = n8 * 8 + cbase;
            float2 q0 = *(float2*)&s_red[r0 * RED_PITCH + cc];
            float2 q1 = *(float2*)&s_red[r1 * RED_PITCH + cc];
            float2 v0 = {tf32r((oacc[n8][0] + q0.x) * inv0), tf32r((oacc[n8][1] + q0.y) * inv0)};
            float2 v1 = {tf32r((oacc[n8][2] + q1.x) * inv1), tf32r((oacc[n8][3] + q1.y) * inv1)};
            *(float2*)&P[((size_t)(t0 + r0) * BX + b) * EE + h * DH + cc] = v0;
            *(float2*)&P[((size_t)(t0 + r1) * BX + b) * EE + h * DH + cc] = v1;
        }
    }

    // rescale this block's attn rows (unnormalized -> probabilities)
    if (attn_out) {
        const int r = tid >> 2;
        const int l4 = tid & 3;
        const float inv = s_sum[r];
        float* row = attn_out + ((size_t)bh * TT + t0 + r) * SS;
#pragma unroll 8
        for (int i = 0; i < 64; i++) {
            float4 v = *(float4*)&row[l4 * 4 + i * 16];
            v.x *= inv; v.y *= inv; v.z *= inv; v.w *= inv;
            *(float4*)&row[l4 * 4 + i * 16] = v;
        }
    }
}

// ---------------------------------------------------------------------------
// Launch
// ---------------------------------------------------------------------------
extern "C" void kernel_launch(void* const* d_in, const int* in_sizes, int n_in,
                              void* d_out, int out_size)
{
    const float* src   = (const float*)d_in[0];
    const float* tgt   = (const float*)d_in[1];
    const float* spad  = (const float*)d_in[2];
    const float* tpad  = (const float*)d_in[3];
    const float* amask = (const float*)d_in[4];
    const int*   caus  = (const int*)  d_in[5];
    const float* Wq    = (const float*)d_in[6];
    const float* Wk    = (const float*)d_in[7];
    const float* Wv    = (const float*)d_in[8];
    const float* Wo    = (const float*)d_in[9];
    const float* bo    = (const float*)d_in[10];

    const size_t OUT_N  = (size_t)TT * BX * EE;
    const size_t ATTN_N = (size_t)BX * HH * TT * SS;

    float* out_p  = nullptr;
    float* attn_p = nullptr;
    if ((size_t)out_size == OUT_N + ATTN_N) {
        out_p  = (float*)d_out;
        attn_p = (float*)d_out + OUT_N;
    } else if ((size_t)out_size == ATTN_N) {
        attn_p = (float*)d_out;
    } else {
        out_p  = (float*)d_out;
    }

    float *Qp, *Kp, *Vtp, *Pp, *Wtp, *Arp, *Brp;
    cudaGetSymbolAddress((void**)&Qp, g_Q);
    cudaGetSymbolAddress((void**)&Kp, g_K);
    cudaGetSymbolAddress((void**)&Vtp, g_Vt);
    cudaGetSymbolAddress((void**)&Pp, g_P);
    cudaGetSymbolAddress((void**)&Wtp, g_Wt);
    cudaGetSymbolAddress((void**)&Arp, g_Ar);
    cudaGetSymbolAddress((void**)&Brp, g_Br);

    const int ATTN_SMEM = ATTN2_FLOATS * (int)sizeof(float);
    cudaFuncSetAttribute(attn_kernel, cudaFuncAttributeMaxDynamicSharedMemorySize, ATTN_SMEM);
    cudaFuncSetAttribute(gemm_qkv_kernel, cudaFuncAttributeMaxDynamicSharedMemorySize, GSMEM);
    cudaFuncSetAttribute(gemm_out_kernel, cudaFuncAttributeMaxDynamicSharedMemorySize, GSMEM);

    // pre-round inputs + transpose weights
    round_tf32_kernel<<<dim3(512, 1, 2), 256>>>(tgt, src, Arp, Brp);
    transpose_tf32_kernel<<<dim3(32, 32, 4), 256>>>(Wq, Wk, Wv, Wo, Wtp);

    // merged QKV projections
    gemm_qkv_kernel<<<dim3(8, 32, 3), 256, GSMEM>>>(Arp, Brp, Wtp, Qp, Kp, Vtp);

    // fused attention (2 CTAs/SM)
    dim3 agrid(TT / AT2, BX * HH);   // (16, 64)
    attn_kernel<<<agrid, dim3(256), ATTN_SMEM>>>(Qp, Kp, Vtp, tpad, spad, amask,
                                                 caus, attn_p, Pp);

    // output projection
    if (out_p) {
        gemm_out_kernel<<<dim3(8, 32), 256, GSMEM>>>(Pp, Wtp + 3 * (size_t)EE * EE, bo, out_p);
    }
}

// round 10
// speedup vs baseline: 1.0461x; 1.0461x over previous
#include <cuda_runtime.h>
#include <cuda_bf16.h>
#include <math.h>
#include <cstdint>

// Problem constants
#define BX   4
#define TT   1024
#define SS   1024
#define EE   1024
#define HH   16
#define DH   64

// Scratch (device globals; no allocation allowed)
__device__ float g_Q[BX * HH * TT * DH];   // [B,H,T,D]  tf32, pre-scaled by 1/8
__device__ float g_K[BX * HH * SS * DH];   // [B,H,S,D]  tf32
__device__ float g_Vt[BX * HH * DH * SS];  // [B,H,D,S]  tf32
__device__ float g_P[TT * BX * EE];        // [T,B,E]    tf32
__device__ float g_Wt[4 * EE * EE];        // W^T [N,K]  tf32
__device__ float g_Ar[BX * TT * EE];       // tgt tf32-rounded
__device__ float g_Br[BX * SS * EE];       // src tf32-rounded

// ---------------------------------------------------------------------------
// Helpers
// ---------------------------------------------------------------------------
__device__ __forceinline__ uint32_t smem_u32(const void* p) {
    uint32_t a;
    asm("{ .reg .u64 t; cvta.to.shared.u64 t, %1; cvt.u32.u64 %0, t; }" : "=r"(a) : "l"(p));
    return a;
}
__device__ __forceinline__ float tf32r(float x) {
    uint32_t u;
    asm("cvt.rna.tf32.f32 %0, %1;" : "=r"(u) : "f"(x));
    return __uint_as_float(u);
}
#define SWZ128(off) ((off) ^ (((off) >> 3) & 0x70))

__device__ __forceinline__ void cp16(uint32_t dst, const void* src) {
    asm volatile("cp.async.cg.shared.global [%0], [%1], 16;" :: "r"(dst), "l"(src));
}
#define CP_COMMIT() asm volatile("cp.async.commit_group;" ::: "memory")
#define CP_WAIT1()  asm volatile("cp.async.wait_group 1;" ::: "memory")

__device__ __forceinline__ void ldsm4(uint32_t* r, uint32_t addr) {
    asm volatile("ldmatrix.sync.aligned.m8n8.x4.shared.b16 {%0,%1,%2,%3}, [%4];"
                 : "=r"(r[0]), "=r"(r[1]), "=r"(r[2]), "=r"(r[3]) : "r"(addr));
}
__device__ __forceinline__ void mma_tf32(float* d, const uint32_t* a, uint32_t b0, uint32_t b1) {
    asm volatile("mma.sync.aligned.m16n8k8.row.col.f32.tf32.tf32.f32 "
                 "{%0,%1,%2,%3}, {%4,%5,%6,%7}, {%8,%9}, {%0,%1,%2,%3};"
                 : "+f"(d[0]), "+f"(d[1]), "+f"(d[2]), "+f"(d[3])
                 : "r"(a[0]), "r"(a[1]), "r"(a[2]), "r"(a[3]), "r"(b0), "r"(b1));
}

// ---------------------------------------------------------------------------
// Elementwise tf32 rounding copies (z selects tensor)
// ---------------------------------------------------------------------------
__global__ __launch_bounds__(256)
void round_tf32_kernel(const float* __restrict__ a, const float* __restrict__ b,
                       float* __restrict__ oa, float* __restrict__ ob)
{
    const float* src = blockIdx.z ? b : a;
    float* dst = blockIdx.z ? ob : oa;
    const int n4 = (BX * TT * EE) / 4;
    for (int i = blockIdx.x * 256 + threadIdx.x; i < n4; i += gridDim.x * 256) {
        float4 v = ((const float4*)src)[i];
        v.x = tf32r(v.x); v.y = tf32r(v.y); v.z = tf32r(v.z); v.w = tf32r(v.w);
        ((float4*)dst)[i] = v;
    }
}

// ---------------------------------------------------------------------------
// Weight transpose + tf32 round, 4 weights in one launch (z selects)
// ---------------------------------------------------------------------------
__global__ __launch_bounds__(256)
void transpose_tf32_kernel(const float* __restrict__ W0, const float* __restrict__ W1,
                           const float* __restrict__ W2, const float* __restrict__ W3,
                           float* __restrict__ WtBase)
{
    __shared__ float tile[32][33];
    const int z = blockIdx.z;
    const float* W = (z == 0) ? W0 : (z == 1) ? W1 : (z == 2) ? W2 : W3;
    float* Wt = WtBase + (size_t)z * EE * EE;
    const int k0 = blockIdx.y * 32, n0 = blockIdx.x * 32;
    const int tx = threadIdx.x & 31, ty = threadIdx.x >> 5;
#pragma unroll
    for (int t = 0; t < 4; t++)
        tile[ty + 8 * t][tx] = W[(size_t)(k0 + ty + 8 * t) * EE + n0 + tx];
    __syncthreads();
#pragma unroll
    for (int t = 0; t < 4; t++)
        Wt[(size_t)(n0 + ty + 8 * t) * EE + k0 + tx] = tf32r(tile[tx][ty + 8 * t]);
}

// ---------------------------------------------------------------------------
// tf32 mma.sync GEMM body: now 2 CTAs/SM (regs capped at 128 by launch bounds)
// ---------------------------------------------------------------------------
#define GSMEM (3 * 32768 + 1024)

__device__ __forceinline__ void gemm_body(
    const float* __restrict__ A, const float* __restrict__ Bt,
    const float* __restrict__ bias, float* __restrict__ C,
    int mode, float scale, int L)
{
    extern __shared__ char dyn_sm[];
    char* sm = (char*)(((uintptr_t)dyn_sm + 1023) & ~(uintptr_t)1023);
    const uint32_t sb = smem_u32(sm);

    const int tid  = threadIdx.x;
    const int wid  = tid >> 5;
    const int lane = tid & 31;
    const int wm   = wid & 3;
    const int wn   = wid >> 2;
    const int m0 = blockIdx.y * 128;
    const int n0 = blockIdx.x * 128;

    const float* Ap = A  + (size_t)m0 * 1024;
    const float* Bp = Bt + (size_t)n0 * 1024;

    const int lrow  = ((lane >> 3) & 1) * 8 + (lane & 7);
    const int klane = lane >> 4;

    uint32_t aoff[2], asw[2], boff[4], bsw[4];
#pragma unroll
    for (int mt = 0; mt < 2; mt++) {
        int r = wm * 32 + mt * 16 + lrow;
        aoff[mt] = (uint32_t)r * 128;
        asw[mt]  = (uint32_t)(r & 7);
    }
#pragma unroll
    for (int nt = 0; nt < 4; nt++) {
        int r = wn * 64 + nt * 16 + lrow;
        boff[nt] = (uint32_t)r * 128;
        bsw[nt]  = (uint32_t)(r & 7);
    }

    float acc[2][8][4];
#pragma unroll
    for (int mt = 0; mt < 2; mt++)
#pragma unroll
        for (int nt = 0; nt < 8; nt++)
#pragma unroll
            for (int c = 0; c < 4; c++) acc[mt][nt][c] = 0.f;

    auto prefetch = [&](int st, int kt) {
        const int k0 = kt * 32;
        const uint32_t ao = sb + st * 32768;
        const uint32_t bo = ao + 16384;
#pragma unroll
        for (int t = 0; t < 4; t++) {
            int idx = tid + t * 256;
            int r = idx >> 3, c4 = idx & 7;
            uint32_t sw = SWZ128((uint32_t)(r * 128 + c4 * 16));
            cp16(ao + sw, Ap + (size_t)r * 1024 + k0 + c4 * 4);
            cp16(bo + sw, Bp + (size_t)r * 1024 + k0 + c4 * 4);
        }
    };

    prefetch(0, 0); CP_COMMIT();
    prefetch(1, 1); CP_COMMIT();

#pragma unroll 1
    for (int kt = 0; kt < 32; kt++) {
        CP_WAIT1();
        __syncthreads();
        if (kt + 2 < 32) prefetch((kt + 2) % 3, kt + 2);
        CP_COMMIT();

        const uint32_t ab = sb + (kt % 3) * 32768;
        const uint32_t bb = ab + 16384;
#pragma unroll
        for (int k8 = 0; k8 < 4; k8++) {
            const uint32_t kc = (uint32_t)(k8 * 2 + klane);
            uint32_t af[2][4], bf[4][4];
#pragma unroll
            for (int mt = 0; mt < 2; mt++)
                ldsm4(af[mt], ab + aoff[mt] + ((kc ^ asw[mt]) << 4));
#pragma unroll
            for (int nt = 0; nt < 4; nt++)
                ldsm4(bf[nt], bb + boff[nt] + ((kc ^ bsw[nt]) << 4));
#pragma unroll
            for (int mt = 0; mt < 2; mt++)
#pragma unroll
                for (int n8 = 0; n8 < 8; n8++) {
                    int bt = n8 >> 1, sub = n8 & 1;
                    mma_tf32(acc[mt][n8], af[mt], bf[bt][sub], bf[bt][sub + 2]);
                }
        }
    }

    const int rbase = lane >> 2;
    const int cbase = 2 * (lane & 3);
#pragma unroll
    for (int mt = 0; mt < 2; mt++) {
#pragma unroll
        for (int nt = 0; nt < 8; nt++) {
            int n = n0 + wn * 64 + nt * 8 + cbase;
#pragma unroll
            for (int half = 0; half < 2; half++) {
                int m = m0 + wm * 32 + mt * 16 + rbase + half * 8;
                float2 v;
                v.x = acc[mt][nt][half * 2 + 0];
                v.y = acc[mt][nt][half * 2 + 1];
                if (mode == 0) {
                    v.x += bias[n];
                    v.y += bias[n + 1];
                    *(float2*)&C[(size_t)m * 1024 + n] = v;
                } else if (mode == 1) {
                    int b = m / L, l = m % L;
                    size_t o = (((size_t)(b * HH + (n >> 6)) * L + l) * DH) + (n & 63);
                    v.x = tf32r(v.x * scale);
                    v.y = tf32r(v.y * scale);
                    *(float2*)&C[o] = v;
                } else {
                    int b = m / L, s = m % L;
                    size_t o = (((size_t)(b * HH + (n >> 6)) * DH) + (n & 63)) * (size_t)L + s;
                    C[o]     = tf32r(v.x);
                    C[o + L] = tf32r(v.y);
                }
            }
        }
    }
}

__global__ __launch_bounds__(256, 2)
void gemm_qkv_kernel(const float* __restrict__ Atgt, const float* __restrict__ Asrc,
                     const float* __restrict__ Wt,
                     float* __restrict__ Cq, float* __restrict__ Ck, float* __restrict__ Cvt)
{
    const int z = blockIdx.z;
    const float* A = (z == 0) ? Atgt : Asrc;
    const float* W = Wt + (size_t)z * EE * EE;
    float* C = (z == 0) ? Cq : (z == 1) ? Ck : Cvt;
    gemm_body(A, W, nullptr, C, (z == 2) ? 2 : 1, (z == 0) ? 0.125f : 1.0f, (z == 0) ? TT : SS);
}

__global__ __launch_bounds__(256, 2)
void gemm_out_kernel(const float* __restrict__ A, const float* __restrict__ Wt,
                     const float* __restrict__ bias, float* __restrict__ C)
{
    gemm_body(A, Wt, bias, C, 0, 1.0f, TT);
}

// ---------------------------------------------------------------------------
// Fused flash-style attention (R8 structure, verbatim): 256 threads, 2 CTAs/SM.
// One block = (b,h) x 64 t-rows; 16 iterations of 64-column tiles.
// K/V double-buffered cp.async (distance 2, joint commit groups).
// P never touches smem (shuffle permute); PV k-split 2, reduced at end.
// ---------------------------------------------------------------------------
#define AT2 64
// smem float offsets
#define F_Q    0                    // 64x64, rows 256B swizzled      4096
#define F_K    4096                 // 2 x 64x64                      8192
#define F_V    12288                // 2 x 64x64 (V^T d x s)          8192
#define F_SP   20480                // spad row for b                 1024
#define F_PART 21504                // 2 x 64 partial row sums         128
#define F_SUM  21632                // 64 inv sums                      64
#define ATTN2_FLOATS 21696          // 86784 B
#define RED_PITCH 72                // k-split O reduce buffer (reuses F_K)

__global__ __launch_bounds__(256, 2)
void attn_kernel(const float* __restrict__ Q, const float* __restrict__ K,
                 const float* __restrict__ Vt,
                 const float* __restrict__ tpad, const float* __restrict__ spad,
                 const float* __restrict__ amask, const int* __restrict__ causal_p,
                 float* __restrict__ attn_out, float* __restrict__ P)
{
    extern __shared__ float smf[];
    const uint32_t q_b  = smem_u32(smf + F_Q);
    const uint32_t k_b  = smem_u32(smf + F_K);
    const uint32_t v_b  = smem_u32(smf + F_V);
    const uint32_t sp_b = smem_u32(smf + F_SP);
    float* s_sp   = smf + F_SP;
    float* s_part = smf + F_PART;
    float* s_sum  = smf + F_SUM;
    float* s_red  = smf + F_K;      // reused after main loop

    const int tid = threadIdx.x;
    const int bh  = blockIdx.y;
    const int b   = bh >> 4;
    const int h   = bh & 15;
    const int t0  = blockIdx.x * AT2;
    const bool causal = (causal_p[0] != 0);

    const size_t qbase  = ((size_t)bh * TT + t0) * DH;
    const size_t kbase  = (size_t)bh * SS * DH;
    const size_t vtbase = (size_t)bh * DH * SS;

    const int lane  = tid & 31;
    const int wid   = tid >> 5;
    const int wm    = wid & 3;    // m16 group
    const int wn    = wid >> 2;   // n32 group (0/1); also PV k-split id
    const int lrow  = ((lane >> 3) & 1) * 8 + (lane & 7);
    const int klane = lane >> 4;
    const int rbase = lane >> 2;
    const int cbase = 2 * (lane & 3);

    const int r0 = wm * 16 + rbase;
    const int r1 = r0 + 8;
    const float tm0 = tpad[b * TT + t0 + r0];
    const float tm1 = tpad[b * TT + t0 + r1];

    // shuffle sources for C-layout -> A-fragment permute
    const int p_   = lane & 3;
    const int srcA = (lane & 28) | (p_ >> 1);
    const bool oddp = (p_ & 1);

    auto prefetch_kv = [&](int it) {
        const uint32_t kb = k_b + (uint32_t)(it & 1) * 16384;
        const uint32_t vb = v_b + (uint32_t)(it & 1) * 16384;
        const int c0 = it * 64;
#pragma unroll
        for (int t = 0; t < 4; t++) {
            int idx = tid + t * 256;
            int r = idx >> 4, c = idx & 15;
            cp16(kb + r * 256 + ((c ^ (r & 7)) << 4),
                 K + kbase + (size_t)(c0 + r) * DH + c * 4);
            cp16(vb + r * 256 + ((c ^ (r & 7)) << 4),
                 Vt + vtbase + (size_t)r * SS + c0 + c * 4);
        }
    };

    // prologue: Q + spad + KV0 | KV1
    {
#pragma unroll
        for (int t = 0; t < 4; t++) {
            int idx = tid + t * 256;
            int r = idx >> 4, c = idx & 15;
            cp16(q_b + r * 256 + ((c ^ (r & 7)) << 4), Q + qbase + (size_t)r * DH + c * 4);
        }
        cp16(sp_b + tid * 16, spad + b * SS + tid * 4);
    }
    prefetch_kv(0);
    CP_COMMIT();
    prefetch_kv(1);
    CP_COMMIT();

    CP_WAIT1();
    __syncthreads();

    // preload Q fragments (m16 rows wm*16.., k=64)
    const int arow = wm * 16 + lrow;
    uint32_t qf[8][4];
#pragma unroll
    for (int k8 = 0; k8 < 8; k8++) {
        uint32_t kc = (uint32_t)(k8 * 2 + klane);
        ldsm4(qf[k8], q_b + arow * 256 + ((kc ^ (uint32_t)(arow & 7)) << 4));
    }
    const int brow0 = wn * 32 + lrow;        // K rows (first n16 of this n32)
    const int brow1 = brow0 + 16;            // second n16

    float rs0 = 0.f, rs1 = 0.f;
    float oacc[8][4];                        // m16 x n64 partial (own k slice)
#pragma unroll
    for (int n8 = 0; n8 < 8; n8++)
#pragma unroll
        for (int c = 0; c < 4; c++) oacc[n8][c] = 0.f;

#pragma unroll 1
    for (int it = 0; it < 16; it++) {
        if (it > 0) {
            CP_WAIT1();
            __syncthreads();
        }
        const int c0 = it * 64;
        const uint32_t kb = k_b + (uint32_t)(it & 1) * 16384;
        const uint32_t vb = v_b + (uint32_t)(it & 1) * 16384;

        // mask loads early
        float2 am[4][2];
#pragma unroll
        for (int n8 = 0; n8 < 4; n8++) {
            int sc = c0 + wn * 32 + n8 * 8 + cbase;
            am[n8][0] = *(const float2*)&amask[((size_t)b * TT + t0 + r0) * SS + sc];
            am[n8][1] = *(const float2*)&amask[((size_t)b * TT + t0 + r1) * SS + sc];
        }

        // S = Q @ K^T  (warp m16 x n32)
        float acc[4][4];
#pragma unroll
        for (int n8 = 0; n8 < 4; n8++)
#pragma unroll
            for (int c = 0; c < 4; c++) acc[n8][c] = 0.f;

#pragma unroll
        for (int k8 = 0; k8 < 8; k8++) {
            uint32_t kc = (uint32_t)(k8 * 2 + klane);
            uint32_t bf0[4], bf1[4];
            ldsm4(bf0, kb + brow0 * 256 + ((kc ^ (uint32_t)(brow0 & 7)) << 4));
            ldsm4(bf1, kb + brow1 * 256 + ((kc ^ (uint32_t)(brow1 & 7)) << 4));
            mma_tf32(acc[0], qf[k8], bf0[0], bf0[2]);
            mma_tf32(acc[1], qf[k8], bf0[1], bf0[3]);
            mma_tf32(acc[2], qf[k8], bf1[0], bf1[2]);
            mma_tf32(acc[3], qf[k8], bf1[1], bf1[3]);
        }

        // exp (no max shift), attn write (unnormalized), row sums, tf32 round
        const int tg0 = t0 + r0, tg1 = t0 + r1;
#pragma unroll
        for (int n8 = 0; n8 < 4; n8++) {
            int scl = wn * 32 + n8 * 8 + cbase;
            int sc  = c0 + scl;
            float2 sp = *(const float2*)&s_sp[sc];

            float m00 = tm0 * sp.x * am[n8][0].x;
            float m01 = tm0 * sp.y * am[n8][0].y;
            float m10 = tm1 * sp.x * am[n8][1].x;
            float m11 = tm1 * sp.y * am[n8][1].y;
            if (causal) {
                if (sc > tg0)     m00 = 0.f;
                if (sc + 1 > tg0) m01 = 0.f;
                if (sc > tg1)     m10 = 0.f;
                if (sc + 1 > tg1) m11 = 0.f;
            }
            float e00 = __expf(acc[n8][0] + m00);
            float e01 = __expf(acc[n8][1] + m01);
            float e10 = __expf(acc[n8][2] + m10);
            float e11 = __expf(acc[n8][3] + m11);
            rs0 += e00 + e01;
            rs1 += e10 + e11;

            if (attn_out) {
                float2 w0 = {e00, e01}, w1 = {e10, e11};
                *(float2*)&attn_out[((size_t)bh * TT + tg0) * SS + sc] = w0;
                *(float2*)&attn_out[((size_t)bh * TT + tg1) * SS + sc] = w1;
            }
            // keep tf32-rounded P in registers (C layout)
            acc[n8][0] = tf32r(e00);
            acc[n8][1] = tf32r(e01);
            acc[n8][2] = tf32r(e10);
            acc[n8][3] = tf32r(e11);
        }

        // O += P @ V over this warp's own 32 k-columns (A-frags via shuffles)
#pragma unroll
        for (int j = 0; j < 4; j++) {
            float u0 = __shfl_sync(0xffffffffu, acc[j][0], srcA);
            float u1 = __shfl_sync(0xffffffffu, acc[j][1], srcA);
            float v0 = __shfl_sync(0xffffffffu, acc[j][2], srcA);
            float v1 = __shfl_sync(0xffffffffu, acc[j][3], srcA);
            float w0 = __shfl_sync(0xffffffffu, acc[j][0], srcA + 2);
            float w1 = __shfl_sync(0xffffffffu, acc[j][1], srcA + 2);
            float x0 = __shfl_sync(0xffffffffu, acc[j][2], srcA + 2);
            float x1 = __shfl_sync(0xffffffffu, acc[j][3], srcA + 2);
            uint32_t af[4];
            af[0] = __float_as_uint(oddp ? u1 : u0);
            af[1] = __float_as_uint(oddp ? v1 : v0);
            af[2] = __float_as_uint(oddp ? w1 : w0);
            af[3] = __float_as_uint(oddp ? x1 : x0);

            uint32_t kc = (uint32_t)((wn * 4 + j) * 2 + klane);
#pragma unroll
            for (int nt = 0; nt < 4; nt++) {
                int br = nt * 16 + lrow;
                uint32_t bf[4];
                ldsm4(bf, vb + br * 256 + ((kc ^ (uint32_t)(br & 7)) << 4));
                mma_tf32(oacc[2 * nt],     af, bf[0], bf[2]);
                mma_tf32(oacc[2 * nt + 1], af, bf[1], bf[3]);
            }
        }
        __syncthreads();   // K/V reads done before buffers refilled

        if (it + 2 < 16) {
            prefetch_kv(it + 2);
            CP_COMMIT();
        }
    }

    // row-sum reduction: quad shuffle, then 2-way cross-warp via smem
    rs0 += __shfl_xor_sync(0xffffffffu, rs0, 1);
    rs0 += __shfl_xor_sync(0xffffffffu, rs0, 2);
    rs1 += __shfl_xor_sync(0xffffffffu, rs1, 1);
    rs1 += __shfl_xor_sync(0xffffffffu, rs1, 2);
    if ((lane & 3) == 0) {
        s_part[wn * 64 + r0] = rs0;
        s_part[wn * 64 + r1] = rs1;
    }
    // k-split partials: wn==1 stores O partial to s_red (reuses K buffer)
    if (wn == 1) {
#pragma unroll
        for (int n8 = 0; n8 < 8; n8++) {
            int cc = n8 * 8 + cbase;
            *(float2*)&s_red[r0 * RED_PITCH + cc] = *(float2*)&oacc[n8][0];
            *(float2*)&s_red[r1 * RED_PITCH + cc] = *(float2*)&oacc[n8][2];
        }
    }
    if (attn_out) asm volatile("membar.cta;" ::: "memory");
    __syncthreads();
    if (tid < 64) {
        s_sum[tid] = 1.f / (s_part[tid] + s_part[64 + tid]);
    }
    __syncthreads();

    // wn==0 warps: combine k-split partials, scale, write P gmem (tf32)
    if (wn == 0) {
        float inv0 = s_sum[r0], inv1 = s_sum[r1];
#pragma unroll
        for (int n8 = 0; n8 < 8; n8++) {
            int cc = n8 * 8 + cbase;
            float2 q0 = *(float2*)&s_red[r0 * RED_PITCH + cc];
            float2 q1 = *(float2*)&s_red[r1 * RED_PITCH + cc];
            float2 v0 = {tf32r((oacc[n8][0] + q0.x) * inv0), tf32r((oacc[n8][1] + q0.y) * inv0)};
            float2 v1 = {tf32r((oacc[n8][2] + q1.x) * inv1), tf32r((oacc[n8][3] + q1.y) * inv1)};
            *(float2*)&P[((size_t)(t0 + r0) * BX + b) * EE + h * DH + cc] = v0;
            *(float2*)&P[((size_t)(t0 + r1) * BX + b) * EE + h * DH + cc] = v1;
        }
    }

    // rescale this block's attn rows (unnormalized -> probabilities)
    if (attn_out) {
        const int r = tid >> 2;
        const int l4 = tid & 3;
        const float inv = s_sum[r];
        float* row = attn_out + ((size_t)bh * TT + t0 + r) * SS;
#pragma unroll 8
        for (int i = 0; i < 64; i++) {
            float4 v = *(float4*)&row[l4 * 4 + i * 16];
            v.x *= inv; v.y *= inv; v.z *= inv; v.w *= inv;
            *(float4*)&row[l4 * 4 + i * 16] = v;
        }
    }
}

// ---------------------------------------------------------------------------
// Launch
// ---------------------------------------------------------------------------
extern "C" void kernel_launch(void* const* d_in, const int* in_sizes, int n_in,
                              void* d_out, int out_size)
{
    const float* src   = (const float*)d_in[0];
    const float* tgt   = (const float*)d_in[1];
    const float* spad  = (const float*)d_in[2];
    const float* tpad  = (const float*)d_in[3];
    const float* amask = (const float*)d_in[4];
    const int*   caus  = (const int*)  d_in[5];
    const float* Wq    = (const float*)d_in[6];
    const float* Wk    = (const float*)d_in[7];
    const float* Wv    = (const float*)d_in[8];
    const float* Wo    = (const float*)d_in[9];
    const float* bo    = (const float*)d_in[10];

    const size_t OUT_N  = (size_t)TT * BX * EE;
    const size_t ATTN_N = (size_t)BX * HH * TT * SS;

    float* out_p  = nullptr;
    float* attn_p = nullptr;
    if ((size_t)out_size == OUT_N + ATTN_N) {
        out_p  = (float*)d_out;
        attn_p = (float*)d_out + OUT_N;
    } else if ((size_t)out_size == ATTN_N) {
        attn_p = (float*)d_out;
    } else {
        out_p  = (float*)d_out;
    }

    float *Qp, *Kp, *Vtp, *Pp, *Wtp, *Arp, *Brp;
    cudaGetSymbolAddress((void**)&Qp, g_Q);
    cudaGetSymbolAddress((void**)&Kp, g_K);
    cudaGetSymbolAddress((void**)&Vtp, g_Vt);
    cudaGetSymbolAddress((void**)&Pp, g_P);
    cudaGetSymbolAddress((void**)&Wtp, g_Wt);
    cudaGetSymbolAddress((void**)&Arp, g_Ar);
    cudaGetSymbolAddress((void**)&Brp, g_Br);

    const int ATTN_SMEM = ATTN2_FLOATS * (int)sizeof(float);
    cudaFuncSetAttribute(attn_kernel, cudaFuncAttributeMaxDynamicSharedMemorySize, ATTN_SMEM);
    cudaFuncSetAttribute(gemm_qkv_kernel, cudaFuncAttributeMaxDynamicSharedMemorySize, GSMEM);
    cudaFuncSetAttribute(gemm_out_kernel, cudaFuncAttributeMaxDynamicSharedMemorySize, GSMEM);

    // pre-round inputs + transpose weights
    round_tf32_kernel<<<dim3(512, 1, 2), 256>>>(tgt, src, Arp, Brp);
    transpose_tf32_kernel<<<dim3(32, 32, 4), 256>>>(Wq, Wk, Wv, Wo, Wtp);

    // merged QKV projections (2 CTAs/SM)
    gemm_qkv_kernel<<<dim3(8, 32, 3), 256, GSMEM>>>(Arp, Brp, Wtp, Qp, Kp, Vtp);

    // fused attention (2 CTAs/SM)
    dim3 agrid(TT / AT2, BX * HH);   // (16, 64)
    attn_kernel<<<agrid, dim3(256), ATTN_SMEM>>>(Qp, Kp, Vtp, tpad, spad, amask,
                                                 caus, attn_p, Pp);

    // output projection (2 CTAs/SM)
    if (out_p) {
        gemm_out_kernel<<<dim3(8, 32), 256, GSMEM>>>(Pp, Wtp + 3 * (size_t)EE * EE, bo, out_p);
    }
}